// round 13
// baseline (speedup 1.0000x reference)
#include <cuda_runtime.h>
#include <math.h>

// ---------------- problem constants ----------------
#define NATOM 2048
#define NSEQ  512
#define MTOT  200
#define FIN   1600
#define FH    240
#define CH    50      // neighbor chunk within a slice
#define CHP   52      // padded chunk width (float4-friendly)

// D scratch: 2048 x 1600 fp32 = 13.1 MB
__device__ float g_D[(size_t)NATOM * FIN];
__device__ int g_order[NSEQ];

__device__ __forceinline__ float ftanh(float x) {
    float a = fabsf(x);
    float e = __expf(-2.0f * a);
    float r = __fdividef(1.0f - e, 1.0f + e);
    return copysignf(r, x);
}

// ---------------- kernel 1: descriptor + exact embedding + D ----------------
// smem layout (floats):
//   rn    @0     800    (200 x 4 normalized Ri)
//   w0s   @800   25
//   b0s   @825   25
//   (pad) @850   2
//   w1s   @852   1250   (25 x 50)
//   b1s   @2102  50
//   w2s   @2152  5000   (50 x 100)
//   b2s   @7152  100
//   h1t   @7252  2600   (50 x 52, transposed: [k][nbr])
//   U     @9852  5200   (h0t 25x52 -> Gc 52x100 -> xyz 400)
// total 15052 floats = 60208 B  -> 3 CTAs/SM
#define K1_SMEM_FLOATS 15052

__global__ void __launch_bounds__(256) k1_desc(
    const float* __restrict__ ImageDR,
    const int*   __restrict__ itype,
    const float* __restrict__ davg,
    const float* __restrict__ dstd,
    const float* __restrict__ eW0, const float* __restrict__ eb0,
    const float* __restrict__ eW1, const float* __restrict__ eb1,
    const float* __restrict__ eW2, const float* __restrict__ eb2)
{
    extern __shared__ float sm[];
    float* rn  = sm;
    float* w0s = sm + 800;
    float* b0s = sm + 825;
    float* w1s = sm + 852;
    float* b1s = sm + 2102;
    float* w2s = sm + 2152;
    float* b2s = sm + 7152;
    float* h1t = sm + 7252;
    float* U   = sm + 9852;   // h0t | Gc | xyz

    const int atom = blockIdx.x;
    const int n    = atom & (NSEQ - 1);
    const int tid  = threadIdx.x;
    const int t    = itype[n];

    // ---- phase 1: Rn = (Ri - davg)/dstd ----
    const float4* dr4 = (const float4*)ImageDR + (size_t)atom * MTOT;
    const float4* da4 = (const float4*)davg + t * MTOT;
    const float4* sd4 = (const float4*)dstd + t * MTOT;
    for (int m = tid; m < MTOT; m += 256) {
        float4 dr = dr4[m];
        float R  = dr.x;
        float Rs = (R > 1e-5f) ? R : 1.0f;
        float inv = __fdividef(1.0f, Rs);
        float u = (R - 0.5f) * (1.0f / 5.5f);
        float poly = fmaf(-6.0f * u, u, fmaf(15.0f, u, -10.0f));
        float mid = fmaf(u * u * u, poly, 1.0f) * inv;
        float S;
        if (R > 0.0f && R < 0.5f)      S = inv;
        else if (R > 0.5f && R < 6.0f) S = mid;
        else                           S = 0.0f;
        bool msk = fabsf(R) > 1e-5f;
        float sr = msk ? S * inv : 0.0f;
        float4 da = da4[m], sd = sd4[m];
        rn[m * 4 + 0] = __fdividef(S         - da.x, sd.x);
        rn[m * 4 + 1] = __fdividef(sr * dr.y - da.y, sd.y);
        rn[m * 4 + 2] = __fdividef(sr * dr.z - da.z, sd.z);
        rn[m * 4 + 3] = __fdividef(sr * dr.w - da.w, sd.w);
    }

    float accE[2] = {0.0f, 0.0f}; // xyz accumulators (idx = tid, tid+256)

    for (int j = 0; j < 2; j++) {
        __syncthreads();
        const int base = t * 2 + j;
        for (int i = tid; i < 25;   i += 256) { w0s[i] = eW0[base * 25 + i]; b0s[i] = eb0[base * 25 + i]; }
        for (int i = tid; i < 1250; i += 256) w1s[i] = eW1[base * 1250 + i];
        for (int i = tid; i < 50;   i += 256) b1s[i] = eb1[base * 50 + i];
        for (int i = tid; i < 5000; i += 256) w2s[i] = eW2[base * 5000 + i];
        for (int i = tid; i < 100;  i += 256) b2s[i] = eb2[base * 100 + i];
        __syncthreads();

        for (int ch = 0; ch < 2; ch++) {
            const int nb0 = j * 100 + ch * CH;
            float* h0t = U;   // 25 x 52, transposed [k][nbr]

            // ---- h0t[k][nbr] = tanh(s*W0[k] + b0[k]), zero-padded nbr 50,51 ----
            for (int idx = tid; idx < 25 * CHP; idx += 256) {
                int k = idx / CHP, nbr = idx % CHP;
                float v = 0.0f;
                if (nbr < CH) {
                    float s = rn[(nb0 + nbr) * 4];
                    v = ftanh(fmaf(s, w0s[k], b0s[k]));
                }
                h0t[idx] = v;
            }
            __syncthreads();

            // ---- h1t[c][nbr] = tanh(h0@W1 + b1) + h0[c%25], 4 nbr x 2 ch tiles ----
            for (int idx = tid; idx < 13 * 25; idx += 256) {
                int p = idx / 25, cg = idx % 25;
                int c0 = cg * 2, nb = p * 4;
                float bA = b1s[c0], bB = b1s[c0 + 1];
                float4 aA = make_float4(bA, bA, bA, bA);
                float4 aB = make_float4(bB, bB, bB, bB);
                #pragma unroll
                for (int k = 0; k < 25; k++) {
                    float4 h = *reinterpret_cast<const float4*>(h0t + k * CHP + nb);
                    float2 w = *reinterpret_cast<const float2*>(w1s + k * 50 + c0);
                    aA.x = fmaf(h.x, w.x, aA.x);  aB.x = fmaf(h.x, w.y, aB.x);
                    aA.y = fmaf(h.y, w.x, aA.y);  aB.y = fmaf(h.y, w.y, aB.y);
                    aA.z = fmaf(h.z, w.x, aA.z);  aB.z = fmaf(h.z, w.y, aB.z);
                    aA.w = fmaf(h.w, w.x, aA.w);  aB.w = fmaf(h.w, w.y, aB.w);
                }
                float4 rA = *reinterpret_cast<const float4*>(h0t + (c0 % 25) * CHP + nb);
                float4 rB = *reinterpret_cast<const float4*>(h0t + ((c0 + 1) % 25) * CHP + nb);
                float4 oA, oB;
                oA.x = ftanh(aA.x) + rA.x;  oB.x = ftanh(aB.x) + rB.x;
                oA.y = ftanh(aA.y) + rA.y;  oB.y = ftanh(aB.y) + rB.y;
                oA.z = ftanh(aA.z) + rA.z;  oB.z = ftanh(aB.z) + rB.z;
                oA.w = ftanh(aA.w) + rA.w;  oB.w = ftanh(aB.w) + rB.w;
                *reinterpret_cast<float4*>(h1t + c0 * CHP + nb)       = oA;
                *reinterpret_cast<float4*>(h1t + (c0 + 1) * CHP + nb) = oB;
            }
            __syncthreads();  // h0t (=U) dead; U becomes Gc

            // ---- Gc = tanh(h1@W2 + b2) + h1[c%50] : 4 nbr x 4 ch tiles, 2 B/FMA ----
            for (int idx = tid; idx < 13 * 25; idx += 256) {
                int p = idx / 25, cg = idx % 25;
                int c0 = cg * 4, nb = p * 4;
                float4 bb = *reinterpret_cast<const float4*>(b2s + c0);
                float4 a0 = make_float4(bb.x, bb.x, bb.x, bb.x);  // ch c0,   nbrs
                float4 a1 = make_float4(bb.y, bb.y, bb.y, bb.y);  // ch c0+1
                float4 a2 = make_float4(bb.z, bb.z, bb.z, bb.z);
                float4 a3 = make_float4(bb.w, bb.w, bb.w, bb.w);
                #pragma unroll 10
                for (int k = 0; k < 50; k++) {
                    float4 h = *reinterpret_cast<const float4*>(h1t + k * CHP + nb);
                    float4 w = *reinterpret_cast<const float4*>(w2s + k * 100 + c0);
                    a0.x = fmaf(h.x, w.x, a0.x);  a0.y = fmaf(h.y, w.x, a0.y);
                    a0.z = fmaf(h.z, w.x, a0.z);  a0.w = fmaf(h.w, w.x, a0.w);
                    a1.x = fmaf(h.x, w.y, a1.x);  a1.y = fmaf(h.y, w.y, a1.y);
                    a1.z = fmaf(h.z, w.y, a1.z);  a1.w = fmaf(h.w, w.y, a1.w);
                    a2.x = fmaf(h.x, w.z, a2.x);  a2.y = fmaf(h.y, w.z, a2.y);
                    a2.z = fmaf(h.z, w.z, a2.z);  a2.w = fmaf(h.w, w.z, a2.w);
                    a3.x = fmaf(h.x, w.w, a3.x);  a3.y = fmaf(h.y, w.w, a3.y);
                    a3.z = fmaf(h.z, w.w, a3.z);  a3.w = fmaf(h.w, w.w, a3.w);
                }
                float4 r0 = *reinterpret_cast<const float4*>(h1t + ((c0 + 0) % 50) * CHP + nb);
                float4 r1 = *reinterpret_cast<const float4*>(h1t + ((c0 + 1) % 50) * CHP + nb);
                float4 r2 = *reinterpret_cast<const float4*>(h1t + ((c0 + 2) % 50) * CHP + nb);
                float4 r3 = *reinterpret_cast<const float4*>(h1t + ((c0 + 3) % 50) * CHP + nb);
                float4 g;
                // nbr nb+0
                g.x = ftanh(a0.x) + r0.x;  g.y = ftanh(a1.x) + r1.x;
                g.z = ftanh(a2.x) + r2.x;  g.w = ftanh(a3.x) + r3.x;
                *reinterpret_cast<float4*>(U + (nb + 0) * 100 + c0) = g;
                // nbr nb+1
                g.x = ftanh(a0.y) + r0.y;  g.y = ftanh(a1.y) + r1.y;
                g.z = ftanh(a2.y) + r2.y;  g.w = ftanh(a3.y) + r3.y;
                *reinterpret_cast<float4*>(U + (nb + 1) * 100 + c0) = g;
                // nbr nb+2
                g.x = ftanh(a0.z) + r0.z;  g.y = ftanh(a1.z) + r1.z;
                g.z = ftanh(a2.z) + r2.z;  g.w = ftanh(a3.z) + r3.z;
                *reinterpret_cast<float4*>(U + (nb + 2) * 100 + c0) = g;
                // nbr nb+3
                g.x = ftanh(a0.w) + r0.w;  g.y = ftanh(a1.w) + r1.w;
                g.z = ftanh(a2.w) + r2.w;  g.w = ftanh(a3.w) + r3.w;
                *reinterpret_cast<float4*>(U + (nb + 3) * 100 + c0) = g;
            }
            __syncthreads();

            // ---- einsum partial: xyz[k][c] += sum_{m in chunk} rn[m][k]*Gc[m][c] ----
            #pragma unroll
            for (int r = 0; r < 2; r++) {
                int idx = tid + r * 256;
                if (idx < 400) {
                    int k = idx / 100, c = idx % 100;
                    const float* rp = rn + nb0 * 4 + k;
                    const float* gp = U + c;
                    float a = accE[r];
                    #pragma unroll 5
                    for (int m = 0; m < CH; m++)
                        a = fmaf(rp[m * 4], gp[m * 100], a);
                    accE[r] = a;
                }
            }
            __syncthreads();  // Gc dead before next chunk reuses U
        }
    }

    // ---- xyz into U[0..400), then D ----
    #pragma unroll
    for (int r = 0; r < 2; r++) {
        int idx = tid + r * 256;
        if (idx < 400) U[idx] = accE[r] * (1.0f / 200.0f);
    }
    __syncthreads();

    float* Dout = g_D + (size_t)atom * FIN;
    for (int idx = tid; idx < FIN; idx += 256) {
        int c = idx >> 4, d = idx & 15;
        float s = 0.0f;
        #pragma unroll
        for (int k = 0; k < 4; k++)
            s = fmaf(U[k * 100 + c], U[k * 100 + d], s);
        Dout[idx] = s;
    }
}

// ---------------- kernel S: deterministic type-sort of n indices ----------------
__global__ void __launch_bounds__(512) kS_sort(const int* __restrict__ itype)
{
    __shared__ int ts[NSEQ];
    int tid = threadIdx.x;
    ts[tid] = itype[tid];
    __syncthreads();
    int myt = ts[tid];
    int rank = 0;
    for (int m = 0; m < NSEQ; m++) {
        int tm = ts[m];
        rank += (tm < myt) || (tm == myt && m < tid);
    }
    g_order[rank] = tid;
}

// ---------------- kernel 2: fitting network (type-sorted, 16 atoms/block) ----------------
#define KC 160

__global__ void __launch_bounds__(256) k2_fit(
    const int*   __restrict__ itype,
    const float* __restrict__ W0, const float* __restrict__ b0,
    const float* __restrict__ W1, const float* __restrict__ b1,
    const float* __restrict__ W2, const float* __restrict__ b2,
    const float* __restrict__ W3, const float* __restrict__ b3,
    const float* __restrict__ eshift,
    float* __restrict__ out)
{
    __shared__ __align__(16) float ds[16 * KC];
    __shared__ __align__(16) float h[16 * FH];
    __shared__ float red[16 * 8];
    __shared__ int nnS[4];

    const int tid = threadIdx.x;
    const int o = tid;
    const bool active = (o < FH);

    if (tid < 4) nnS[tid] = g_order[blockIdx.x * 4 + tid];
    __syncthreads();
    int nn[4], tt[4];
    #pragma unroll
    for (int ns = 0; ns < 4; ns++) { nn[ns] = nnS[ns]; tt[ns] = itype[nn[ns]]; }
    const bool uni = (tt[0] == tt[1]) && (tt[1] == tt[2]) && (tt[2] == tt[3]);

    float acc[16];

    // ---- layer 0: h = tanh(D @ W0 + b0) ----
    if (active) {
        #pragma unroll
        for (int ns = 0; ns < 4; ns++) {
            float bb = b0[tt[ns] * FH + o];
            #pragma unroll
            for (int b = 0; b < 4; b++) acc[ns * 4 + b] = bb;
        }
    }
    for (int k0 = 0; k0 < FIN; k0 += KC) {
        __syncthreads();
        for (int i = tid; i < 16 * (KC / 4); i += 256) {
            int a = i / (KC / 4), q = i % (KC / 4);
            int ns = a >> 2, b = a & 3;
            const float4* src = (const float4*)(g_D + (size_t)(b * NSEQ + nn[ns]) * FIN + k0);
            reinterpret_cast<float4*>(ds)[a * (KC / 4) + q] = src[q];
        }
        __syncthreads();
        if (active) {
            if (uni) {
                const float* Wp = W0 + (size_t)tt[0] * FIN * FH;
                for (int k = 0; k < KC; k += 4) {
                    float w0_ = Wp[(size_t)(k0 + k + 0) * FH + o];
                    float w1_ = Wp[(size_t)(k0 + k + 1) * FH + o];
                    float w2_ = Wp[(size_t)(k0 + k + 2) * FH + o];
                    float w3_ = Wp[(size_t)(k0 + k + 3) * FH + o];
                    #pragma unroll
                    for (int a = 0; a < 16; a++) {
                        float4 d = reinterpret_cast<const float4*>(ds)[a * (KC / 4) + (k >> 2)];
                        float v = acc[a];
                        v = fmaf(d.x, w0_, v);
                        v = fmaf(d.y, w1_, v);
                        v = fmaf(d.z, w2_, v);
                        v = fmaf(d.w, w3_, v);
                        acc[a] = v;
                    }
                }
            } else {
                for (int k = 0; k < KC; k += 4) {
                    float wA[4], wB[4];
                    #pragma unroll
                    for (int u = 0; u < 4; u++) {
                        wA[u] = W0[(size_t)(k0 + k + u) * FH + o];
                        wB[u] = W0[(size_t)FIN * FH + (size_t)(k0 + k + u) * FH + o];
                    }
                    #pragma unroll
                    for (int ns = 0; ns < 4; ns++) {
                        float s0 = tt[ns] ? wB[0] : wA[0];
                        float s1 = tt[ns] ? wB[1] : wA[1];
                        float s2 = tt[ns] ? wB[2] : wA[2];
                        float s3 = tt[ns] ? wB[3] : wA[3];
                        #pragma unroll
                        for (int b = 0; b < 4; b++) {
                            float4 d = reinterpret_cast<const float4*>(ds)[(ns * 4 + b) * (KC / 4) + (k >> 2)];
                            float v = acc[ns * 4 + b];
                            v = fmaf(d.x, s0, v);
                            v = fmaf(d.y, s1, v);
                            v = fmaf(d.z, s2, v);
                            v = fmaf(d.w, s3, v);
                            acc[ns * 4 + b] = v;
                        }
                    }
                }
            }
        }
    }
    __syncthreads();
    if (active) {
        #pragma unroll
        for (int a = 0; a < 16; a++) h[a * FH + o] = ftanh(acc[a]);
    }
    __syncthreads();

    // ---- layers 1,2: h = h + tanh(h @ Wl + bl) ----
    const float* Wl[2] = {W1, W2};
    const float* bl[2] = {b1, b2};
    for (int L = 0; L < 2; L++) {
        if (active) {
            #pragma unroll
            for (int ns = 0; ns < 4; ns++) {
                float bb = bl[L][tt[ns] * FH + o];
                #pragma unroll
                for (int b = 0; b < 4; b++) acc[ns * 4 + b] = bb;
            }
            if (uni) {
                const float* Wp = Wl[L] + (size_t)tt[0] * FH * FH;
                for (int k = 0; k < FH; k += 4) {
                    float w0_ = Wp[(k + 0) * FH + o];
                    float w1_ = Wp[(k + 1) * FH + o];
                    float w2_ = Wp[(k + 2) * FH + o];
                    float w3_ = Wp[(k + 3) * FH + o];
                    #pragma unroll
                    for (int a = 0; a < 16; a++) {
                        float4 d = reinterpret_cast<const float4*>(h)[a * (FH / 4) + (k >> 2)];
                        float v = acc[a];
                        v = fmaf(d.x, w0_, v);
                        v = fmaf(d.y, w1_, v);
                        v = fmaf(d.z, w2_, v);
                        v = fmaf(d.w, w3_, v);
                        acc[a] = v;
                    }
                }
            } else {
                for (int k = 0; k < FH; k += 4) {
                    float wA[4], wB[4];
                    #pragma unroll
                    for (int u = 0; u < 4; u++) {
                        wA[u] = Wl[L][(k + u) * FH + o];
                        wB[u] = Wl[L][FH * FH + (k + u) * FH + o];
                    }
                    #pragma unroll
                    for (int ns = 0; ns < 4; ns++) {
                        float s0 = tt[ns] ? wB[0] : wA[0];
                        float s1 = tt[ns] ? wB[1] : wA[1];
                        float s2 = tt[ns] ? wB[2] : wA[2];
                        float s3 = tt[ns] ? wB[3] : wA[3];
                        #pragma unroll
                        for (int b = 0; b < 4; b++) {
                            float4 d = reinterpret_cast<const float4*>(h)[(ns * 4 + b) * (FH / 4) + (k >> 2)];
                            float v = acc[ns * 4 + b];
                            v = fmaf(d.x, s0, v);
                            v = fmaf(d.y, s1, v);
                            v = fmaf(d.z, s2, v);
                            v = fmaf(d.w, s3, v);
                            acc[ns * 4 + b] = v;
                        }
                    }
                }
            }
        }
        __syncthreads();
        if (active) {
            #pragma unroll
            for (int a = 0; a < 16; a++)
                h[a * FH + o] = h[a * FH + o] + ftanh(acc[a]);
        }
        __syncthreads();
    }

    // ---- layer 3: e = h @ W3 + b3 + shift ----
    float w3a = 0.0f, w3b = 0.0f;
    if (active) { w3a = W3[o]; w3b = W3[FH + o]; }
    const int lane = tid & 31, w = tid >> 5;
    #pragma unroll
    for (int a = 0; a < 16; a++) {
        int ns = a >> 2;
        float v = active ? h[a * FH + o] * (tt[ns] ? w3b : w3a) : 0.0f;
        #pragma unroll
        for (int off = 16; off > 0; off >>= 1)
            v += __shfl_down_sync(0xffffffffu, v, off);
        if (lane == 0) red[a * 8 + w] = v;
    }
    __syncthreads();
    if (tid < 16) {
        float s = 0.0f;
        #pragma unroll
        for (int ww = 0; ww < 8; ww++) s += red[tid * 8 + ww];
        int ns = tid >> 2, b = tid & 3;
        int t = tt[ns];
        float e = s + b3[t] + eshift[t];
        out[4 + b * NSEQ + nn[ns]] = e;
    }
}

// ---------------- kernel 3: Etot ----------------
__global__ void k3_etot(float* __restrict__ out)
{
    const int b = blockIdx.x, tid = threadIdx.x;
    __shared__ float red[8];
    float s = 0.0f;
    for (int i = tid; i < NSEQ; i += 256) s += out[4 + b * NSEQ + i];
    #pragma unroll
    for (int off = 16; off > 0; off >>= 1)
        s += __shfl_down_sync(0xffffffffu, s, off);
    if ((tid & 31) == 0) red[tid >> 5] = s;
    __syncthreads();
    if (tid == 0) {
        float tot = 0.0f;
        #pragma unroll
        for (int w = 0; w < 8; w++) tot += red[w];
        out[b] = tot;
    }
}

// ---------------- launch ----------------
extern "C" void kernel_launch(void* const* d_in, const int* in_sizes, int n_in,
                              void* d_out, int out_size)
{
    const int*   itype   = (const int*)d_in[1];
    const float* ImageDR = (const float*)d_in[3];
    const float* davg    = (const float*)d_in[5];
    const float* dstd    = (const float*)d_in[6];
    const float* eW0     = (const float*)d_in[7];
    const float* eb0     = (const float*)d_in[8];
    const float* eW1     = (const float*)d_in[9];
    const float* eb1     = (const float*)d_in[10];
    const float* eW2     = (const float*)d_in[11];
    const float* eb2     = (const float*)d_in[12];
    const float* fW0     = (const float*)d_in[13];
    const float* fb0     = (const float*)d_in[14];
    const float* fW1     = (const float*)d_in[15];
    const float* fb1     = (const float*)d_in[16];
    const float* fW2     = (const float*)d_in[17];
    const float* fb2     = (const float*)d_in[18];
    const float* fW3     = (const float*)d_in[19];
    const float* fb3     = (const float*)d_in[20];
    const float* esh     = (const float*)d_in[21];
    float* out = (float*)d_out;

    size_t smem1 = (size_t)K1_SMEM_FLOATS * sizeof(float);
    cudaFuncSetAttribute(k1_desc, cudaFuncAttributeMaxDynamicSharedMemorySize, (int)smem1);

    k1_desc<<<NATOM, 256, smem1>>>(ImageDR, itype, davg, dstd,
                                   eW0, eb0, eW1, eb1, eW2, eb2);
    kS_sort<<<1, NSEQ>>>(itype);
    k2_fit<<<NSEQ / 4, 256>>>(itype, fW0, fb0, fW1, fb1, fW2, fb2, fW3, fb3, esh, out);
    k3_etot<<<4, 256>>>(out);
}

// round 14
// speedup vs baseline: 1.0028x; 1.0028x over previous
#include <cuda_runtime.h>
#include <math.h>

// ---------------- problem constants ----------------
#define NATOM 2048
#define NSEQ  512
#define MTOT  200
#define FIN   1600
#define FH    240
#define CH    50      // neighbor chunk within a slice
#define CHP   52      // padded chunk width (float4-friendly)

// D scratch: 2048 x 1600 fp32 = 13.1 MB
__device__ float g_D[(size_t)NATOM * FIN];
__device__ int g_order[NSEQ];

__device__ __forceinline__ float ftanh(float x) {
    float a = fabsf(x);
    float e = __expf(-2.0f * a);
    float r = __fdividef(1.0f - e, 1.0f + e);
    return copysignf(r, x);
}

// ---------------- kernel 1: descriptor + exact embedding + D ----------------
// smem layout (floats):
//   rn    @0     800    (200 x 4 normalized Ri)
//   w0s   @800   25
//   b0s   @825   25
//   (pad) @850   2
//   w1s   @852   1250   (25 x 50)
//   b1s   @2102  50
//   w2s   @2152  5000   (50 x 100)
//   b2s   @7152  100
//   h1t   @7252  2600   (50 x 52, transposed: [k][nbr])
//   U     @9852  5200   (h0t 25x52 -> Gc 52x100 -> xyz 400)
// total 15052 floats = 60208 B  -> 3 CTAs/SM
#define K1_SMEM_FLOATS 15052

__global__ void __launch_bounds__(256) k1_desc(
    const float* __restrict__ ImageDR,
    const int*   __restrict__ itype,
    const float* __restrict__ davg,
    const float* __restrict__ dstd,
    const float* __restrict__ eW0, const float* __restrict__ eb0,
    const float* __restrict__ eW1, const float* __restrict__ eb1,
    const float* __restrict__ eW2, const float* __restrict__ eb2)
{
    extern __shared__ float sm[];
    float* rn  = sm;
    float* w0s = sm + 800;
    float* b0s = sm + 825;
    float* w1s = sm + 852;
    float* b1s = sm + 2102;
    float* w2s = sm + 2152;
    float* b2s = sm + 7152;
    float* h1t = sm + 7252;
    float* U   = sm + 9852;   // h0t | Gc | xyz

    const int atom = blockIdx.x;
    const int n    = atom & (NSEQ - 1);
    const int tid  = threadIdx.x;
    const int t    = itype[n];

    // ---- phase 1: Rn = (Ri - davg)/dstd ----
    const float4* dr4 = (const float4*)ImageDR + (size_t)atom * MTOT;
    const float4* da4 = (const float4*)davg + t * MTOT;
    const float4* sd4 = (const float4*)dstd + t * MTOT;
    for (int m = tid; m < MTOT; m += 256) {
        float4 dr = dr4[m];
        float R  = dr.x;
        float Rs = (R > 1e-5f) ? R : 1.0f;
        float inv = __fdividef(1.0f, Rs);
        float u = (R - 0.5f) * (1.0f / 5.5f);
        float poly = fmaf(-6.0f * u, u, fmaf(15.0f, u, -10.0f));
        float mid = fmaf(u * u * u, poly, 1.0f) * inv;
        float S;
        if (R > 0.0f && R < 0.5f)      S = inv;
        else if (R > 0.5f && R < 6.0f) S = mid;
        else                           S = 0.0f;
        bool msk = fabsf(R) > 1e-5f;
        float sr = msk ? S * inv : 0.0f;
        float4 da = da4[m], sd = sd4[m];
        rn[m * 4 + 0] = __fdividef(S         - da.x, sd.x);
        rn[m * 4 + 1] = __fdividef(sr * dr.y - da.y, sd.y);
        rn[m * 4 + 2] = __fdividef(sr * dr.z - da.z, sd.z);
        rn[m * 4 + 3] = __fdividef(sr * dr.w - da.w, sd.w);
    }

    float accE[2] = {0.0f, 0.0f}; // xyz accumulators (idx = tid, tid+256)

    for (int j = 0; j < 2; j++) {
        __syncthreads();
        const int base = t * 2 + j;
        for (int i = tid; i < 25;   i += 256) { w0s[i] = eW0[base * 25 + i]; b0s[i] = eb0[base * 25 + i]; }
        for (int i = tid; i < 1250; i += 256) w1s[i] = eW1[base * 1250 + i];
        for (int i = tid; i < 50;   i += 256) b1s[i] = eb1[base * 50 + i];
        for (int i = tid; i < 5000; i += 256) w2s[i] = eW2[base * 5000 + i];
        for (int i = tid; i < 100;  i += 256) b2s[i] = eb2[base * 100 + i];
        __syncthreads();

        for (int ch = 0; ch < 2; ch++) {
            const int nb0 = j * 100 + ch * CH;
            float* h0t = U;   // 25 x 52, transposed [k][nbr]

            // ---- h0t[k][nbr] = tanh(s*W0[k] + b0[k]), zero-padded nbr 50,51 ----
            for (int idx = tid; idx < 25 * CHP; idx += 256) {
                int k = idx / CHP, nbr = idx % CHP;
                float v = 0.0f;
                if (nbr < CH) {
                    float s = rn[(nb0 + nbr) * 4];
                    v = ftanh(fmaf(s, w0s[k], b0s[k]));
                }
                h0t[idx] = v;
            }
            __syncthreads();

            // ---- h1t[c][nbr] = tanh(h0@W1 + b1) + h0[c%25], 4 nbr x 2 ch tiles ----
            for (int idx = tid; idx < 13 * 25; idx += 256) {
                int p = idx / 25, cg = idx % 25;
                int c0 = cg * 2, nb = p * 4;
                float bA = b1s[c0], bB = b1s[c0 + 1];
                float4 aA = make_float4(bA, bA, bA, bA);
                float4 aB = make_float4(bB, bB, bB, bB);
                #pragma unroll
                for (int k = 0; k < 25; k++) {
                    float4 h = *reinterpret_cast<const float4*>(h0t + k * CHP + nb);
                    float2 w = *reinterpret_cast<const float2*>(w1s + k * 50 + c0);
                    aA.x = fmaf(h.x, w.x, aA.x);  aB.x = fmaf(h.x, w.y, aB.x);
                    aA.y = fmaf(h.y, w.x, aA.y);  aB.y = fmaf(h.y, w.y, aB.y);
                    aA.z = fmaf(h.z, w.x, aA.z);  aB.z = fmaf(h.z, w.y, aB.z);
                    aA.w = fmaf(h.w, w.x, aA.w);  aB.w = fmaf(h.w, w.y, aB.w);
                }
                float4 rA = *reinterpret_cast<const float4*>(h0t + (c0 % 25) * CHP + nb);
                float4 rB = *reinterpret_cast<const float4*>(h0t + ((c0 + 1) % 25) * CHP + nb);
                float4 oA, oB;
                oA.x = ftanh(aA.x) + rA.x;  oB.x = ftanh(aB.x) + rB.x;
                oA.y = ftanh(aA.y) + rA.y;  oB.y = ftanh(aB.y) + rB.y;
                oA.z = ftanh(aA.z) + rA.z;  oB.z = ftanh(aB.z) + rB.z;
                oA.w = ftanh(aA.w) + rA.w;  oB.w = ftanh(aB.w) + rB.w;
                *reinterpret_cast<float4*>(h1t + c0 * CHP + nb)       = oA;
                *reinterpret_cast<float4*>(h1t + (c0 + 1) * CHP + nb) = oB;
            }
            __syncthreads();  // h0t (=U) dead; U becomes Gc

            // ---- Gc = tanh(h1@W2 + b2) + h1[c%50] : 4 nbr x 4 ch tiles, 2 B/FMA ----
            for (int idx = tid; idx < 13 * 25; idx += 256) {
                int p = idx / 25, cg = idx % 25;
                int c0 = cg * 4, nb = p * 4;
                float4 bb = *reinterpret_cast<const float4*>(b2s + c0);
                float4 a0 = make_float4(bb.x, bb.x, bb.x, bb.x);  // ch c0,   nbrs
                float4 a1 = make_float4(bb.y, bb.y, bb.y, bb.y);  // ch c0+1
                float4 a2 = make_float4(bb.z, bb.z, bb.z, bb.z);
                float4 a3 = make_float4(bb.w, bb.w, bb.w, bb.w);
                #pragma unroll 10
                for (int k = 0; k < 50; k++) {
                    float4 h = *reinterpret_cast<const float4*>(h1t + k * CHP + nb);
                    float4 w = *reinterpret_cast<const float4*>(w2s + k * 100 + c0);
                    a0.x = fmaf(h.x, w.x, a0.x);  a0.y = fmaf(h.y, w.x, a0.y);
                    a0.z = fmaf(h.z, w.x, a0.z);  a0.w = fmaf(h.w, w.x, a0.w);
                    a1.x = fmaf(h.x, w.y, a1.x);  a1.y = fmaf(h.y, w.y, a1.y);
                    a1.z = fmaf(h.z, w.y, a1.z);  a1.w = fmaf(h.w, w.y, a1.w);
                    a2.x = fmaf(h.x, w.z, a2.x);  a2.y = fmaf(h.y, w.z, a2.y);
                    a2.z = fmaf(h.z, w.z, a2.z);  a2.w = fmaf(h.w, w.z, a2.w);
                    a3.x = fmaf(h.x, w.w, a3.x);  a3.y = fmaf(h.y, w.w, a3.y);
                    a3.z = fmaf(h.z, w.w, a3.z);  a3.w = fmaf(h.w, w.w, a3.w);
                }
                float4 r0 = *reinterpret_cast<const float4*>(h1t + ((c0 + 0) % 50) * CHP + nb);
                float4 r1 = *reinterpret_cast<const float4*>(h1t + ((c0 + 1) % 50) * CHP + nb);
                float4 r2 = *reinterpret_cast<const float4*>(h1t + ((c0 + 2) % 50) * CHP + nb);
                float4 r3 = *reinterpret_cast<const float4*>(h1t + ((c0 + 3) % 50) * CHP + nb);
                float4 g;
                // nbr nb+0
                g.x = ftanh(a0.x) + r0.x;  g.y = ftanh(a1.x) + r1.x;
                g.z = ftanh(a2.x) + r2.x;  g.w = ftanh(a3.x) + r3.x;
                *reinterpret_cast<float4*>(U + (nb + 0) * 100 + c0) = g;
                // nbr nb+1
                g.x = ftanh(a0.y) + r0.y;  g.y = ftanh(a1.y) + r1.y;
                g.z = ftanh(a2.y) + r2.y;  g.w = ftanh(a3.y) + r3.y;
                *reinterpret_cast<float4*>(U + (nb + 1) * 100 + c0) = g;
                // nbr nb+2
                g.x = ftanh(a0.z) + r0.z;  g.y = ftanh(a1.z) + r1.z;
                g.z = ftanh(a2.z) + r2.z;  g.w = ftanh(a3.z) + r3.z;
                *reinterpret_cast<float4*>(U + (nb + 2) * 100 + c0) = g;
                // nbr nb+3
                g.x = ftanh(a0.w) + r0.w;  g.y = ftanh(a1.w) + r1.w;
                g.z = ftanh(a2.w) + r2.w;  g.w = ftanh(a3.w) + r3.w;
                *reinterpret_cast<float4*>(U + (nb + 3) * 100 + c0) = g;
            }
            __syncthreads();

            // ---- einsum partial: xyz[k][c] += sum_{m in chunk} rn[m][k]*Gc[m][c] ----
            #pragma unroll
            for (int r = 0; r < 2; r++) {
                int idx = tid + r * 256;
                if (idx < 400) {
                    int k = idx / 100, c = idx % 100;
                    const float* rp = rn + nb0 * 4 + k;
                    const float* gp = U + c;
                    float a = accE[r];
                    #pragma unroll 5
                    for (int m = 0; m < CH; m++)
                        a = fmaf(rp[m * 4], gp[m * 100], a);
                    accE[r] = a;
                }
            }
            __syncthreads();  // Gc dead before next chunk reuses U
        }
    }

    // ---- xyz into U[0..400), then D ----
    #pragma unroll
    for (int r = 0; r < 2; r++) {
        int idx = tid + r * 256;
        if (idx < 400) U[idx] = accE[r] * (1.0f / 200.0f);
    }
    __syncthreads();

    float* Dout = g_D + (size_t)atom * FIN;
    for (int idx = tid; idx < FIN; idx += 256) {
        int c = idx >> 4, d = idx & 15;
        float s = 0.0f;
        #pragma unroll
        for (int k = 0; k < 4; k++)
            s = fmaf(U[k * 100 + c], U[k * 100 + d], s);
        Dout[idx] = s;
    }
}

// ---------------- kernel S: deterministic type-sort of n indices ----------------
__global__ void __launch_bounds__(512) kS_sort(const int* __restrict__ itype)
{
    __shared__ int ts[NSEQ];
    int tid = threadIdx.x;
    ts[tid] = itype[tid];
    __syncthreads();
    int myt = ts[tid];
    int rank = 0;
    for (int m = 0; m < NSEQ; m++) {
        int tm = ts[m];
        rank += (tm < myt) || (tm == myt && m < tid);
    }
    g_order[rank] = tid;
}

// ---------------- kernel 2: fitting network (type-sorted, 16 atoms/block) ----------------
#define KC 160

__global__ void __launch_bounds__(256) k2_fit(
    const int*   __restrict__ itype,
    const float* __restrict__ W0, const float* __restrict__ b0,
    const float* __restrict__ W1, const float* __restrict__ b1,
    const float* __restrict__ W2, const float* __restrict__ b2,
    const float* __restrict__ W3, const float* __restrict__ b3,
    const float* __restrict__ eshift,
    float* __restrict__ out)
{
    __shared__ __align__(16) float ds[16 * KC];
    __shared__ __align__(16) float h[16 * FH];
    __shared__ float red[16 * 8];
    __shared__ int nnS[4];

    const int tid = threadIdx.x;
    const int o = tid;
    const bool active = (o < FH);

    if (tid < 4) nnS[tid] = g_order[blockIdx.x * 4 + tid];
    __syncthreads();
    int nn[4], tt[4];
    #pragma unroll
    for (int ns = 0; ns < 4; ns++) { nn[ns] = nnS[ns]; tt[ns] = itype[nn[ns]]; }
    const bool uni = (tt[0] == tt[1]) && (tt[1] == tt[2]) && (tt[2] == tt[3]);

    float acc[16];

    // ---- layer 0: h = tanh(D @ W0 + b0) ----
    if (active) {
        #pragma unroll
        for (int ns = 0; ns < 4; ns++) {
            float bb = b0[tt[ns] * FH + o];
            #pragma unroll
            for (int b = 0; b < 4; b++) acc[ns * 4 + b] = bb;
        }
    }
    for (int k0 = 0; k0 < FIN; k0 += KC) {
        __syncthreads();
        for (int i = tid; i < 16 * (KC / 4); i += 256) {
            int a = i / (KC / 4), q = i % (KC / 4);
            int ns = a >> 2, b = a & 3;
            const float4* src = (const float4*)(g_D + (size_t)(b * NSEQ + nn[ns]) * FIN + k0);
            reinterpret_cast<float4*>(ds)[a * (KC / 4) + q] = src[q];
        }
        __syncthreads();
        if (active) {
            if (uni) {
                const float* Wp = W0 + (size_t)tt[0] * FIN * FH;
                for (int k = 0; k < KC; k += 4) {
                    float w0_ = Wp[(size_t)(k0 + k + 0) * FH + o];
                    float w1_ = Wp[(size_t)(k0 + k + 1) * FH + o];
                    float w2_ = Wp[(size_t)(k0 + k + 2) * FH + o];
                    float w3_ = Wp[(size_t)(k0 + k + 3) * FH + o];
                    #pragma unroll
                    for (int a = 0; a < 16; a++) {
                        float4 d = reinterpret_cast<const float4*>(ds)[a * (KC / 4) + (k >> 2)];
                        float v = acc[a];
                        v = fmaf(d.x, w0_, v);
                        v = fmaf(d.y, w1_, v);
                        v = fmaf(d.z, w2_, v);
                        v = fmaf(d.w, w3_, v);
                        acc[a] = v;
                    }
                }
            } else {
                for (int k = 0; k < KC; k += 4) {
                    float wA[4], wB[4];
                    #pragma unroll
                    for (int u = 0; u < 4; u++) {
                        wA[u] = W0[(size_t)(k0 + k + u) * FH + o];
                        wB[u] = W0[(size_t)FIN * FH + (size_t)(k0 + k + u) * FH + o];
                    }
                    #pragma unroll
                    for (int ns = 0; ns < 4; ns++) {
                        float s0 = tt[ns] ? wB[0] : wA[0];
                        float s1 = tt[ns] ? wB[1] : wA[1];
                        float s2 = tt[ns] ? wB[2] : wA[2];
                        float s3 = tt[ns] ? wB[3] : wA[3];
                        #pragma unroll
                        for (int b = 0; b < 4; b++) {
                            float4 d = reinterpret_cast<const float4*>(ds)[(ns * 4 + b) * (KC / 4) + (k >> 2)];
                            float v = acc[ns * 4 + b];
                            v = fmaf(d.x, s0, v);
                            v = fmaf(d.y, s1, v);
                            v = fmaf(d.z, s2, v);
                            v = fmaf(d.w, s3, v);
                            acc[ns * 4 + b] = v;
                        }
                    }
                }
            }
        }
    }
    __syncthreads();
    if (active) {
        #pragma unroll
        for (int a = 0; a < 16; a++) h[a * FH + o] = ftanh(acc[a]);
    }
    __syncthreads();

    // ---- layers 1,2: h = h + tanh(h @ Wl + bl) ----
    const float* Wl[2] = {W1, W2};
    const float* bl[2] = {b1, b2};
    for (int L = 0; L < 2; L++) {
        if (active) {
            #pragma unroll
            for (int ns = 0; ns < 4; ns++) {
                float bb = bl[L][tt[ns] * FH + o];
                #pragma unroll
                for (int b = 0; b < 4; b++) acc[ns * 4 + b] = bb;
            }
            if (uni) {
                const float* Wp = Wl[L] + (size_t)tt[0] * FH * FH;
                for (int k = 0; k < FH; k += 4) {
                    float w0_ = Wp[(k + 0) * FH + o];
                    float w1_ = Wp[(k + 1) * FH + o];
                    float w2_ = Wp[(k + 2) * FH + o];
                    float w3_ = Wp[(k + 3) * FH + o];
                    #pragma unroll
                    for (int a = 0; a < 16; a++) {
                        float4 d = reinterpret_cast<const float4*>(h)[a * (FH / 4) + (k >> 2)];
                        float v = acc[a];
                        v = fmaf(d.x, w0_, v);
                        v = fmaf(d.y, w1_, v);
                        v = fmaf(d.z, w2_, v);
                        v = fmaf(d.w, w3_, v);
                        acc[a] = v;
                    }
                }
            } else {
                for (int k = 0; k < FH; k += 4) {
                    float wA[4], wB[4];
                    #pragma unroll
                    for (int u = 0; u < 4; u++) {
                        wA[u] = Wl[L][(k + u) * FH + o];
                        wB[u] = Wl[L][FH * FH + (k + u) * FH + o];
                    }
                    #pragma unroll
                    for (int ns = 0; ns < 4; ns++) {
                        float s0 = tt[ns] ? wB[0] : wA[0];
                        float s1 = tt[ns] ? wB[1] : wA[1];
                        float s2 = tt[ns] ? wB[2] : wA[2];
                        float s3 = tt[ns] ? wB[3] : wA[3];
                        #pragma unroll
                        for (int b = 0; b < 4; b++) {
                            float4 d = reinterpret_cast<const float4*>(h)[(ns * 4 + b) * (FH / 4) + (k >> 2)];
                            float v = acc[ns * 4 + b];
                            v = fmaf(d.x, s0, v);
                            v = fmaf(d.y, s1, v);
                            v = fmaf(d.z, s2, v);
                            v = fmaf(d.w, s3, v);
                            acc[ns * 4 + b] = v;
                        }
                    }
                }
            }
        }
        __syncthreads();
        if (active) {
            #pragma unroll
            for (int a = 0; a < 16; a++)
                h[a * FH + o] = h[a * FH + o] + ftanh(acc[a]);
        }
        __syncthreads();
    }

    // ---- layer 3: e = h @ W3 + b3 + shift ----
    float w3a = 0.0f, w3b = 0.0f;
    if (active) { w3a = W3[o]; w3b = W3[FH + o]; }
    const int lane = tid & 31, w = tid >> 5;
    #pragma unroll
    for (int a = 0; a < 16; a++) {
        int ns = a >> 2;
        float v = active ? h[a * FH + o] * (tt[ns] ? w3b : w3a) : 0.0f;
        #pragma unroll
        for (int off = 16; off > 0; off >>= 1)
            v += __shfl_down_sync(0xffffffffu, v, off);
        if (lane == 0) red[a * 8 + w] = v;
    }
    __syncthreads();
    if (tid < 16) {
        float s = 0.0f;
        #pragma unroll
        for (int ww = 0; ww < 8; ww++) s += red[tid * 8 + ww];
        int ns = tid >> 2, b = tid & 3;
        int t = tt[ns];
        float e = s + b3[t] + eshift[t];
        out[4 + b * NSEQ + nn[ns]] = e;
    }
}

// ---------------- kernel 3: Etot ----------------
__global__ void k3_etot(float* __restrict__ out)
{
    const int b = blockIdx.x, tid = threadIdx.x;
    __shared__ float red[8];
    float s = 0.0f;
    for (int i = tid; i < NSEQ; i += 256) s += out[4 + b * NSEQ + i];
    #pragma unroll
    for (int off = 16; off > 0; off >>= 1)
        s += __shfl_down_sync(0xffffffffu, s, off);
    if ((tid & 31) == 0) red[tid >> 5] = s;
    __syncthreads();
    if (tid == 0) {
        float tot = 0.0f;
        #pragma unroll
        for (int w = 0; w < 8; w++) tot += red[w];
        out[b] = tot;
    }
}

// ---------------- launch ----------------
extern "C" void kernel_launch(void* const* d_in, const int* in_sizes, int n_in,
                              void* d_out, int out_size)
{
    const int*   itype   = (const int*)d_in[1];
    const float* ImageDR = (const float*)d_in[3];
    const float* davg    = (const float*)d_in[5];
    const float* dstd    = (const float*)d_in[6];
    const float* eW0     = (const float*)d_in[7];
    const float* eb0     = (const float*)d_in[8];
    const float* eW1     = (const float*)d_in[9];
    const float* eb1     = (const float*)d_in[10];
    const float* eW2     = (const float*)d_in[11];
    const float* eb2     = (const float*)d_in[12];
    const float* fW0     = (const float*)d_in[13];
    const float* fb0     = (const float*)d_in[14];
    const float* fW1     = (const float*)d_in[15];
    const float* fb1     = (const float*)d_in[16];
    const float* fW2     = (const float*)d_in[17];
    const float* fb2     = (const float*)d_in[18];
    const float* fW3     = (const float*)d_in[19];
    const float* fb3     = (const float*)d_in[20];
    const float* esh     = (const float*)d_in[21];
    float* out = (float*)d_out;

    size_t smem1 = (size_t)K1_SMEM_FLOATS * sizeof(float);
    cudaFuncSetAttribute(k1_desc, cudaFuncAttributeMaxDynamicSharedMemorySize, (int)smem1);

    k1_desc<<<NATOM, 256, smem1>>>(ImageDR, itype, davg, dstd,
                                   eW0, eb0, eW1, eb1, eW2, eb2);
    kS_sort<<<1, NSEQ>>>(itype);
    k2_fit<<<NSEQ / 4, 256>>>(itype, fW0, fb0, fW1, fb1, fW2, fb2, fW3, fb3, esh, out);
    k3_etot<<<4, 256>>>(out);
}

// round 15
// speedup vs baseline: 1.0044x; 1.0015x over previous
#include <cuda_runtime.h>
#include <math.h>

// ---------------- problem constants ----------------
#define NATOM 2048
#define NSEQ  512
#define MTOT  200
#define FIN   1600
#define FH    240
#define CH    50      // neighbor chunk within a slice
#define CHP   52      // padded chunk width (float4-friendly)

// D scratch: 2048 x 1600 fp32 = 13.1 MB
__device__ float g_D[(size_t)NATOM * FIN];
__device__ int g_order[NSEQ];

__device__ __forceinline__ float ftanh(float x) {
    float a = fabsf(x);
    float e = __expf(-2.0f * a);
    float r = __fdividef(1.0f - e, 1.0f + e);
    return copysignf(r, x);
}

// ---------------- kernel 1: descriptor + exact embedding + D ----------------
// smem layout (floats):
//   rn    @0     800    (200 x 4 normalized Ri)
//   w0s   @800   25
//   b0s   @825   25
//   (pad) @850   2
//   w1s   @852   1250   (25 x 50)
//   b1s   @2102  50
//   w2s   @2152  5000   (50 x 100)
//   b2s   @7152  100
//   h1t   @7252  2600   (50 x 52, transposed: [k][nbr])
//   U     @9852  5200   (h0t 25x52 -> Gc 52x100 -> xyz 400)
// total 15052 floats = 60208 B  -> 3 CTAs/SM
#define K1_SMEM_FLOATS 15052

__global__ void __launch_bounds__(256) k1_desc(
    const float* __restrict__ ImageDR,
    const int*   __restrict__ itype,
    const float* __restrict__ davg,
    const float* __restrict__ dstd,
    const float* __restrict__ eW0, const float* __restrict__ eb0,
    const float* __restrict__ eW1, const float* __restrict__ eb1,
    const float* __restrict__ eW2, const float* __restrict__ eb2)
{
    extern __shared__ float sm[];
    float* rn  = sm;
    float* w0s = sm + 800;
    float* b0s = sm + 825;
    float* w1s = sm + 852;
    float* b1s = sm + 2102;
    float* w2s = sm + 2152;
    float* b2s = sm + 7152;
    float* h1t = sm + 7252;
    float* U   = sm + 9852;   // h0t | Gc | xyz

    const int atom = blockIdx.x;
    const int n    = atom & (NSEQ - 1);
    const int tid  = threadIdx.x;
    const int t    = itype[n];

    // ---- phase 1: Rn = (Ri - davg)/dstd ----
    const float4* dr4 = (const float4*)ImageDR + (size_t)atom * MTOT;
    const float4* da4 = (const float4*)davg + t * MTOT;
    const float4* sd4 = (const float4*)dstd + t * MTOT;
    for (int m = tid; m < MTOT; m += 256) {
        float4 dr = dr4[m];
        float R  = dr.x;
        float Rs = (R > 1e-5f) ? R : 1.0f;
        float inv = __fdividef(1.0f, Rs);
        float u = (R - 0.5f) * (1.0f / 5.5f);
        float poly = fmaf(-6.0f * u, u, fmaf(15.0f, u, -10.0f));
        float mid = fmaf(u * u * u, poly, 1.0f) * inv;
        float S;
        if (R > 0.0f && R < 0.5f)      S = inv;
        else if (R > 0.5f && R < 6.0f) S = mid;
        else                           S = 0.0f;
        bool msk = fabsf(R) > 1e-5f;
        float sr = msk ? S * inv : 0.0f;
        float4 da = da4[m], sd = sd4[m];
        rn[m * 4 + 0] = __fdividef(S         - da.x, sd.x);
        rn[m * 4 + 1] = __fdividef(sr * dr.y - da.y, sd.y);
        rn[m * 4 + 2] = __fdividef(sr * dr.z - da.z, sd.z);
        rn[m * 4 + 3] = __fdividef(sr * dr.w - da.w, sd.w);
    }

    float accE[2] = {0.0f, 0.0f}; // xyz accumulators (idx = tid, tid+256)

    for (int j = 0; j < 2; j++) {
        __syncthreads();
        const int base = t * 2 + j;
        for (int i = tid; i < 25;   i += 256) { w0s[i] = eW0[base * 25 + i]; b0s[i] = eb0[base * 25 + i]; }
        for (int i = tid; i < 1250; i += 256) w1s[i] = eW1[base * 1250 + i];
        for (int i = tid; i < 50;   i += 256) b1s[i] = eb1[base * 50 + i];
        for (int i = tid; i < 5000; i += 256) w2s[i] = eW2[base * 5000 + i];
        for (int i = tid; i < 100;  i += 256) b2s[i] = eb2[base * 100 + i];
        __syncthreads();

        for (int ch = 0; ch < 2; ch++) {
            const int nb0 = j * 100 + ch * CH;
            float* h0t = U;   // 25 x 52, transposed [k][nbr]

            // ---- h0t[k][nbr] = tanh(s*W0[k] + b0[k]), zero-padded nbr 50,51 ----
            for (int idx = tid; idx < 25 * CHP; idx += 256) {
                int k = idx / CHP, nbr = idx % CHP;
                float v = 0.0f;
                if (nbr < CH) {
                    float s = rn[(nb0 + nbr) * 4];
                    v = ftanh(fmaf(s, w0s[k], b0s[k]));
                }
                h0t[idx] = v;
            }
            __syncthreads();

            // ---- h1t[c][nbr] = tanh(h0@W1 + b1) + h0[c%25], 4 nbr x 2 ch tiles ----
            for (int idx = tid; idx < 13 * 25; idx += 256) {
                int p = idx / 25, cg = idx % 25;
                int c0 = cg * 2, nb = p * 4;
                float bA = b1s[c0], bB = b1s[c0 + 1];
                float4 aA = make_float4(bA, bA, bA, bA);
                float4 aB = make_float4(bB, bB, bB, bB);
                #pragma unroll
                for (int k = 0; k < 25; k++) {
                    float4 h = *reinterpret_cast<const float4*>(h0t + k * CHP + nb);
                    float2 w = *reinterpret_cast<const float2*>(w1s + k * 50 + c0);
                    aA.x = fmaf(h.x, w.x, aA.x);  aB.x = fmaf(h.x, w.y, aB.x);
                    aA.y = fmaf(h.y, w.x, aA.y);  aB.y = fmaf(h.y, w.y, aB.y);
                    aA.z = fmaf(h.z, w.x, aA.z);  aB.z = fmaf(h.z, w.y, aB.z);
                    aA.w = fmaf(h.w, w.x, aA.w);  aB.w = fmaf(h.w, w.y, aB.w);
                }
                float4 rA = *reinterpret_cast<const float4*>(h0t + (c0 % 25) * CHP + nb);
                float4 rB = *reinterpret_cast<const float4*>(h0t + ((c0 + 1) % 25) * CHP + nb);
                float4 oA, oB;
                oA.x = ftanh(aA.x) + rA.x;  oB.x = ftanh(aB.x) + rB.x;
                oA.y = ftanh(aA.y) + rA.y;  oB.y = ftanh(aB.y) + rB.y;
                oA.z = ftanh(aA.z) + rA.z;  oB.z = ftanh(aB.z) + rB.z;
                oA.w = ftanh(aA.w) + rA.w;  oB.w = ftanh(aB.w) + rB.w;
                *reinterpret_cast<float4*>(h1t + c0 * CHP + nb)       = oA;
                *reinterpret_cast<float4*>(h1t + (c0 + 1) * CHP + nb) = oB;
            }
            __syncthreads();  // h0t (=U) dead; U becomes Gc

            // ---- Gc = tanh(h1@W2 + b2) + h1[c%50] : 4 nbr x 4 ch tiles, 2 B/FMA ----
            for (int idx = tid; idx < 13 * 25; idx += 256) {
                int p = idx / 25, cg = idx % 25;
                int c0 = cg * 4, nb = p * 4;
                float4 bb = *reinterpret_cast<const float4*>(b2s + c0);
                float4 a0 = make_float4(bb.x, bb.x, bb.x, bb.x);  // ch c0,   nbrs
                float4 a1 = make_float4(bb.y, bb.y, bb.y, bb.y);  // ch c0+1
                float4 a2 = make_float4(bb.z, bb.z, bb.z, bb.z);
                float4 a3 = make_float4(bb.w, bb.w, bb.w, bb.w);
                #pragma unroll 10
                for (int k = 0; k < 50; k++) {
                    float4 h = *reinterpret_cast<const float4*>(h1t + k * CHP + nb);
                    float4 w = *reinterpret_cast<const float4*>(w2s + k * 100 + c0);
                    a0.x = fmaf(h.x, w.x, a0.x);  a0.y = fmaf(h.y, w.x, a0.y);
                    a0.z = fmaf(h.z, w.x, a0.z);  a0.w = fmaf(h.w, w.x, a0.w);
                    a1.x = fmaf(h.x, w.y, a1.x);  a1.y = fmaf(h.y, w.y, a1.y);
                    a1.z = fmaf(h.z, w.y, a1.z);  a1.w = fmaf(h.w, w.y, a1.w);
                    a2.x = fmaf(h.x, w.z, a2.x);  a2.y = fmaf(h.y, w.z, a2.y);
                    a2.z = fmaf(h.z, w.z, a2.z);  a2.w = fmaf(h.w, w.z, a2.w);
                    a3.x = fmaf(h.x, w.w, a3.x);  a3.y = fmaf(h.y, w.w, a3.y);
                    a3.z = fmaf(h.z, w.w, a3.z);  a3.w = fmaf(h.w, w.w, a3.w);
                }
                float4 r0 = *reinterpret_cast<const float4*>(h1t + ((c0 + 0) % 50) * CHP + nb);
                float4 r1 = *reinterpret_cast<const float4*>(h1t + ((c0 + 1) % 50) * CHP + nb);
                float4 r2 = *reinterpret_cast<const float4*>(h1t + ((c0 + 2) % 50) * CHP + nb);
                float4 r3 = *reinterpret_cast<const float4*>(h1t + ((c0 + 3) % 50) * CHP + nb);
                float4 g;
                // nbr nb+0
                g.x = ftanh(a0.x) + r0.x;  g.y = ftanh(a1.x) + r1.x;
                g.z = ftanh(a2.x) + r2.x;  g.w = ftanh(a3.x) + r3.x;
                *reinterpret_cast<float4*>(U + (nb + 0) * 100 + c0) = g;
                // nbr nb+1
                g.x = ftanh(a0.y) + r0.y;  g.y = ftanh(a1.y) + r1.y;
                g.z = ftanh(a2.y) + r2.y;  g.w = ftanh(a3.y) + r3.y;
                *reinterpret_cast<float4*>(U + (nb + 1) * 100 + c0) = g;
                // nbr nb+2
                g.x = ftanh(a0.z) + r0.z;  g.y = ftanh(a1.z) + r1.z;
                g.z = ftanh(a2.z) + r2.z;  g.w = ftanh(a3.z) + r3.z;
                *reinterpret_cast<float4*>(U + (nb + 2) * 100 + c0) = g;
                // nbr nb+3
                g.x = ftanh(a0.w) + r0.w;  g.y = ftanh(a1.w) + r1.w;
                g.z = ftanh(a2.w) + r2.w;  g.w = ftanh(a3.w) + r3.w;
                *reinterpret_cast<float4*>(U + (nb + 3) * 100 + c0) = g;
            }
            __syncthreads();

            // ---- einsum partial: xyz[k][c] += sum_{m in chunk} rn[m][k]*Gc[m][c] ----
            #pragma unroll
            for (int r = 0; r < 2; r++) {
                int idx = tid + r * 256;
                if (idx < 400) {
                    int k = idx / 100, c = idx % 100;
                    const float* rp = rn + nb0 * 4 + k;
                    const float* gp = U + c;
                    float a = accE[r];
                    #pragma unroll 5
                    for (int m = 0; m < CH; m++)
                        a = fmaf(rp[m * 4], gp[m * 100], a);
                    accE[r] = a;
                }
            }
            __syncthreads();  // Gc dead before next chunk reuses U
        }
    }

    // ---- xyz into U[0..400), then D ----
    #pragma unroll
    for (int r = 0; r < 2; r++) {
        int idx = tid + r * 256;
        if (idx < 400) U[idx] = accE[r] * (1.0f / 200.0f);
    }
    __syncthreads();

    float* Dout = g_D + (size_t)atom * FIN;
    for (int idx = tid; idx < FIN; idx += 256) {
        int c = idx >> 4, d = idx & 15;
        float s = 0.0f;
        #pragma unroll
        for (int k = 0; k < 4; k++)
            s = fmaf(U[k * 100 + c], U[k * 100 + d], s);
        Dout[idx] = s;
    }
}

// ---------------- kernel S: deterministic type-sort of n indices ----------------
__global__ void __launch_bounds__(512) kS_sort(const int* __restrict__ itype)
{
    __shared__ int ts[NSEQ];
    int tid = threadIdx.x;
    ts[tid] = itype[tid];
    __syncthreads();
    int myt = ts[tid];
    int rank = 0;
    for (int m = 0; m < NSEQ; m++) {
        int tm = ts[m];
        rank += (tm < myt) || (tm == myt && m < tid);
    }
    g_order[rank] = tid;
}

// ---------------- kernel 2: fitting network (type-sorted, 16 atoms/block) ----------------
#define KC 160

__global__ void __launch_bounds__(256) k2_fit(
    const int*   __restrict__ itype,
    const float* __restrict__ W0, const float* __restrict__ b0,
    const float* __restrict__ W1, const float* __restrict__ b1,
    const float* __restrict__ W2, const float* __restrict__ b2,
    const float* __restrict__ W3, const float* __restrict__ b3,
    const float* __restrict__ eshift,
    float* __restrict__ out)
{
    __shared__ __align__(16) float ds[16 * KC];
    __shared__ __align__(16) float h[16 * FH];
    __shared__ float red[16 * 8];
    __shared__ int nnS[4];

    const int tid = threadIdx.x;
    const int o = tid;
    const bool active = (o < FH);

    if (tid < 4) nnS[tid] = g_order[blockIdx.x * 4 + tid];
    __syncthreads();
    int nn[4], tt[4];
    #pragma unroll
    for (int ns = 0; ns < 4; ns++) { nn[ns] = nnS[ns]; tt[ns] = itype[nn[ns]]; }
    const bool uni = (tt[0] == tt[1]) && (tt[1] == tt[2]) && (tt[2] == tt[3]);

    float acc[16];

    // ---- layer 0: h = tanh(D @ W0 + b0) ----
    if (active) {
        #pragma unroll
        for (int ns = 0; ns < 4; ns++) {
            float bb = b0[tt[ns] * FH + o];
            #pragma unroll
            for (int b = 0; b < 4; b++) acc[ns * 4 + b] = bb;
        }
    }
    for (int k0 = 0; k0 < FIN; k0 += KC) {
        __syncthreads();
        for (int i = tid; i < 16 * (KC / 4); i += 256) {
            int a = i / (KC / 4), q = i % (KC / 4);
            int ns = a >> 2, b = a & 3;
            const float4* src = (const float4*)(g_D + (size_t)(b * NSEQ + nn[ns]) * FIN + k0);
            reinterpret_cast<float4*>(ds)[a * (KC / 4) + q] = src[q];
        }
        __syncthreads();
        if (active) {
            if (uni) {
                const float* Wp = W0 + (size_t)tt[0] * FIN * FH;
                for (int k = 0; k < KC; k += 4) {
                    float w0_ = Wp[(size_t)(k0 + k + 0) * FH + o];
                    float w1_ = Wp[(size_t)(k0 + k + 1) * FH + o];
                    float w2_ = Wp[(size_t)(k0 + k + 2) * FH + o];
                    float w3_ = Wp[(size_t)(k0 + k + 3) * FH + o];
                    #pragma unroll
                    for (int a = 0; a < 16; a++) {
                        float4 d = reinterpret_cast<const float4*>(ds)[a * (KC / 4) + (k >> 2)];
                        float v = acc[a];
                        v = fmaf(d.x, w0_, v);
                        v = fmaf(d.y, w1_, v);
                        v = fmaf(d.z, w2_, v);
                        v = fmaf(d.w, w3_, v);
                        acc[a] = v;
                    }
                }
            } else {
                for (int k = 0; k < KC; k += 4) {
                    float wA[4], wB[4];
                    #pragma unroll
                    for (int u = 0; u < 4; u++) {
                        wA[u] = W0[(size_t)(k0 + k + u) * FH + o];
                        wB[u] = W0[(size_t)FIN * FH + (size_t)(k0 + k + u) * FH + o];
                    }
                    #pragma unroll
                    for (int ns = 0; ns < 4; ns++) {
                        float s0 = tt[ns] ? wB[0] : wA[0];
                        float s1 = tt[ns] ? wB[1] : wA[1];
                        float s2 = tt[ns] ? wB[2] : wA[2];
                        float s3 = tt[ns] ? wB[3] : wA[3];
                        #pragma unroll
                        for (int b = 0; b < 4; b++) {
                            float4 d = reinterpret_cast<const float4*>(ds)[(ns * 4 + b) * (KC / 4) + (k >> 2)];
                            float v = acc[ns * 4 + b];
                            v = fmaf(d.x, s0, v);
                            v = fmaf(d.y, s1, v);
                            v = fmaf(d.z, s2, v);
                            v = fmaf(d.w, s3, v);
                            acc[ns * 4 + b] = v;
                        }
                    }
                }
            }
        }
    }
    __syncthreads();
    if (active) {
        #pragma unroll
        for (int a = 0; a < 16; a++) h[a * FH + o] = ftanh(acc[a]);
    }
    __syncthreads();

    // ---- layers 1,2: h = h + tanh(h @ Wl + bl) ----
    const float* Wl[2] = {W1, W2};
    const float* bl[2] = {b1, b2};
    for (int L = 0; L < 2; L++) {
        if (active) {
            #pragma unroll
            for (int ns = 0; ns < 4; ns++) {
                float bb = bl[L][tt[ns] * FH + o];
                #pragma unroll
                for (int b = 0; b < 4; b++) acc[ns * 4 + b] = bb;
            }
            if (uni) {
                const float* Wp = Wl[L] + (size_t)tt[0] * FH * FH;
                for (int k = 0; k < FH; k += 4) {
                    float w0_ = Wp[(k + 0) * FH + o];
                    float w1_ = Wp[(k + 1) * FH + o];
                    float w2_ = Wp[(k + 2) * FH + o];
                    float w3_ = Wp[(k + 3) * FH + o];
                    #pragma unroll
                    for (int a = 0; a < 16; a++) {
                        float4 d = reinterpret_cast<const float4*>(h)[a * (FH / 4) + (k >> 2)];
                        float v = acc[a];
                        v = fmaf(d.x, w0_, v);
                        v = fmaf(d.y, w1_, v);
                        v = fmaf(d.z, w2_, v);
                        v = fmaf(d.w, w3_, v);
                        acc[a] = v;
                    }
                }
            } else {
                for (int k = 0; k < FH; k += 4) {
                    float wA[4], wB[4];
                    #pragma unroll
                    for (int u = 0; u < 4; u++) {
                        wA[u] = Wl[L][(k + u) * FH + o];
                        wB[u] = Wl[L][FH * FH + (k + u) * FH + o];
                    }
                    #pragma unroll
                    for (int ns = 0; ns < 4; ns++) {
                        float s0 = tt[ns] ? wB[0] : wA[0];
                        float s1 = tt[ns] ? wB[1] : wA[1];
                        float s2 = tt[ns] ? wB[2] : wA[2];
                        float s3 = tt[ns] ? wB[3] : wA[3];
                        #pragma unroll
                        for (int b = 0; b < 4; b++) {
                            float4 d = reinterpret_cast<const float4*>(h)[(ns * 4 + b) * (FH / 4) + (k >> 2)];
                            float v = acc[ns * 4 + b];
                            v = fmaf(d.x, s0, v);
                            v = fmaf(d.y, s1, v);
                            v = fmaf(d.z, s2, v);
                            v = fmaf(d.w, s3, v);
                            acc[ns * 4 + b] = v;
                        }
                    }
                }
            }
        }
        __syncthreads();
        if (active) {
            #pragma unroll
            for (int a = 0; a < 16; a++)
                h[a * FH + o] = h[a * FH + o] + ftanh(acc[a]);
        }
        __syncthreads();
    }

    // ---- layer 3: e = h @ W3 + b3 + shift ----
    float w3a = 0.0f, w3b = 0.0f;
    if (active) { w3a = W3[o]; w3b = W3[FH + o]; }
    const int lane = tid & 31, w = tid >> 5;
    #pragma unroll
    for (int a = 0; a < 16; a++) {
        int ns = a >> 2;
        float v = active ? h[a * FH + o] * (tt[ns] ? w3b : w3a) : 0.0f;
        #pragma unroll
        for (int off = 16; off > 0; off >>= 1)
            v += __shfl_down_sync(0xffffffffu, v, off);
        if (lane == 0) red[a * 8 + w] = v;
    }
    __syncthreads();
    if (tid < 16) {
        float s = 0.0f;
        #pragma unroll
        for (int ww = 0; ww < 8; ww++) s += red[tid * 8 + ww];
        int ns = tid >> 2, b = tid & 3;
        int t = tt[ns];
        float e = s + b3[t] + eshift[t];
        out[4 + b * NSEQ + nn[ns]] = e;
    }
}

// ---------------- kernel 3: Etot ----------------
__global__ void k3_etot(float* __restrict__ out)
{
    const int b = blockIdx.x, tid = threadIdx.x;
    __shared__ float red[8];
    float s = 0.0f;
    for (int i = tid; i < NSEQ; i += 256) s += out[4 + b * NSEQ + i];
    #pragma unroll
    for (int off = 16; off > 0; off >>= 1)
        s += __shfl_down_sync(0xffffffffu, s, off);
    if ((tid & 31) == 0) red[tid >> 5] = s;
    __syncthreads();
    if (tid == 0) {
        float tot = 0.0f;
        #pragma unroll
        for (int w = 0; w < 8; w++) tot += red[w];
        out[b] = tot;
    }
}

// ---------------- launch ----------------
extern "C" void kernel_launch(void* const* d_in, const int* in_sizes, int n_in,
                              void* d_out, int out_size)
{
    const int*   itype   = (const int*)d_in[1];
    const float* ImageDR = (const float*)d_in[3];
    const float* davg    = (const float*)d_in[5];
    const float* dstd    = (const float*)d_in[6];
    const float* eW0     = (const float*)d_in[7];
    const float* eb0     = (const float*)d_in[8];
    const float* eW1     = (const float*)d_in[9];
    const float* eb1     = (const float*)d_in[10];
    const float* eW2     = (const float*)d_in[11];
    const float* eb2     = (const float*)d_in[12];
    const float* fW0     = (const float*)d_in[13];
    const float* fb0     = (const float*)d_in[14];
    const float* fW1     = (const float*)d_in[15];
    const float* fb1     = (const float*)d_in[16];
    const float* fW2     = (const float*)d_in[17];
    const float* fb2     = (const float*)d_in[18];
    const float* fW3     = (const float*)d_in[19];
    const float* fb3     = (const float*)d_in[20];
    const float* esh     = (const float*)d_in[21];
    float* out = (float*)d_out;

    size_t smem1 = (size_t)K1_SMEM_FLOATS * sizeof(float);
    cudaFuncSetAttribute(k1_desc, cudaFuncAttributeMaxDynamicSharedMemorySize, (int)smem1);

    k1_desc<<<NATOM, 256, smem1>>>(ImageDR, itype, davg, dstd,
                                   eW0, eb0, eW1, eb1, eW2, eb2);
    kS_sort<<<1, NSEQ>>>(itype);
    k2_fit<<<NSEQ / 4, 256>>>(itype, fW0, fb0, fW1, fb1, fW2, fb2, fW3, fb3, esh, out);
    k3_etot<<<4, 256>>>(out);
}